// round 6
// baseline (speedup 1.0000x reference)
#include <cuda_runtime.h>
#include <cstdint>

// patches: [N=128, C=4, P=32, P, P] f32
// vol:     [B=2,  C=4, H=128, H, H] f32
// centers: [N, 3] i32 ; lower = center - 16 (in [0, 96])
// out = 0.5 * (vol + sum of covering patches)   -- gather, one pass, no atomics.

#define C_DIM 4
#define P_DIM 32
#define H_DIM 128

// per-patch strides in float4 units
#define PATCH_F4   32768u   // C*P^3/4
#define PC_F4      8192u    // P^3/4   (channel stride)
#define PI_F4      256u     // P^2/4   (i stride)
#define PJ_F4      8u       // P/4     (j stride)

// Block = (b, x, y-quarter): 2*128*4 = 1024 blocks of 256 threads.
// Block filters the 64 patches to those overlapping (x, [y0,y0+31]) once,
// then each warp processes 4 y-lines against the short candidate list.
__global__ void __launch_bounds__(256)
pi_fused_kernel(const float4* __restrict__ patches4,
                const float4* __restrict__ vol4,
                const int*    __restrict__ centers,
                float4*       __restrict__ out4)
{
    __shared__ int      s_cnt;
    __shared__ unsigned s_base[64];   // p*PATCH_F4 + dx*PI_F4  (float4 units)
    __shared__ int      s_lo1[64];
    __shared__ int      s_lo2[64];

    const unsigned blk  = blockIdx.x;
    const unsigned b    = blk >> 9;           // 512 blocks per batch
    const unsigned rem  = blk & 511u;
    const unsigned x    = rem >> 2;           // 0..127
    const unsigned y0   = (rem & 3u) << 5;    // 0,32,64,96
    const unsigned lane = threadIdx.x & 31u;
    const unsigned wid  = threadIdx.x >> 5;

    if (threadIdx.x == 0) s_cnt = 0;
    __syncthreads();

    // cooperative filter: threads 0..63 test one patch each
    if (threadIdx.x < 64u) {
        unsigned n = b * 64u + threadIdx.x;
        int lo0 = centers[n * 3 + 0] - (P_DIM / 2);
        int lo1 = centers[n * 3 + 1] - (P_DIM / 2);
        int lo2 = centers[n * 3 + 2] - (P_DIM / 2);
        unsigned dx = (unsigned)((int)x - lo0);
        bool hit_x = dx < 32u;
        bool hit_y = (unsigned)(lo1 - (int)y0 + 31) < 63u;  // windows overlap
        if (hit_x && hit_y) {
            int idx = atomicAdd(&s_cnt, 1);
            s_base[idx] = threadIdx.x * PATCH_F4 + dx * PI_F4;
            s_lo1[idx]  = lo1;
            s_lo2[idx]  = lo2;
        }
    }
    __syncthreads();

    const int ncand = s_cnt;
    const float4 Z = make_float4(0.f,0.f,0.f,0.f);
    const float4* pb = patches4 + (size_t)b * 64u * PATCH_F4;
    const size_t cstr = (size_t)H_DIM * H_DIM * (H_DIM / 4);

    #define ACCUM_CASE(EX0,EY0,EZ0,EW0)                                        \
        {                                                                       \
            const float4* pr0 = prow + 0u * PC_F4;                              \
            const float4* pr1 = prow + 1u * PC_F4;                              \
            const float4* pr2 = prow + 2u * PC_F4;                              \
            const float4* pr3 = prow + 3u * PC_F4;                              \
            float4 L0 = vL ? __ldg(pr0 + (m-1)) : Z;                            \
            float4 R0 = vR ? __ldg(pr0 + m)     : Z;                            \
            float4 L1 = vL ? __ldg(pr1 + (m-1)) : Z;                            \
            float4 R1 = vR ? __ldg(pr1 + m)     : Z;                            \
            float4 L2 = vL ? __ldg(pr2 + (m-1)) : Z;                            \
            float4 R2 = vR ? __ldg(pr2 + m)     : Z;                            \
            float4 L3 = vL ? __ldg(pr3 + (m-1)) : Z;                            \
            float4 R3 = vR ? __ldg(pr3 + m)     : Z;                            \
            acc0.x += EX0(L0,R0); acc0.y += EY0(L0,R0);                         \
            acc0.z += EZ0(L0,R0); acc0.w += EW0(L0,R0);                         \
            acc1.x += EX0(L1,R1); acc1.y += EY0(L1,R1);                         \
            acc1.z += EZ0(L1,R1); acc1.w += EW0(L1,R1);                         \
            acc2.x += EX0(L2,R2); acc2.y += EY0(L2,R2);                         \
            acc2.z += EZ0(L2,R2); acc2.w += EW0(L2,R2);                         \
            acc3.x += EX0(L3,R3); acc3.y += EY0(L3,R3);                         \
            acc3.z += EZ0(L3,R3); acc3.w += EW0(L3,R3);                         \
        }

    #define SEL_RX(L,R) (R.x)
    #define SEL_RY(L,R) (R.y)
    #define SEL_RZ(L,R) (R.z)
    #define SEL_RW(L,R) (R.w)
    #define SEL_LY(L,R) (L.y)
    #define SEL_LZ(L,R) (L.z)
    #define SEL_LW(L,R) (L.w)

    // each warp owns 4 consecutive y-lines
    #pragma unroll 1
    for (int yy = 0; yy < 4; yy++) {
        const int y = (int)y0 + (int)wid * 4 + yy;

        float4 acc0 = Z, acc1 = Z, acc2 = Z, acc3 = Z;

        #pragma unroll 1
        for (int cI = 0; cI < ncand; cI++) {
            unsigned dy = (unsigned)(y - s_lo1[cI]);
            if (dy >= 32u) continue;              // warp-uniform
            const int lo2 = s_lo2[cI];
            const int m   = (int)lane - (lo2 >> 2);
            const unsigned s = (unsigned)lo2 & 3u;
            const bool vL = (unsigned)(m - 1) < 8u;
            const bool vR = (unsigned)m < 8u;
            const float4* prow = pb + s_base[cI] + dy * PJ_F4;

            switch (s) {                           // warp-uniform
            case 0u:  ACCUM_CASE(SEL_RX, SEL_RY, SEL_RZ, SEL_RW) break;
            case 1u:  ACCUM_CASE(SEL_LW, SEL_RX, SEL_RY, SEL_RZ) break;
            case 2u:  ACCUM_CASE(SEL_LZ, SEL_LW, SEL_RX, SEL_RY) break;
            default:  ACCUM_CASE(SEL_LY, SEL_LZ, SEL_LW, SEL_RX) break;
            }
        }

        // epilogue: out = 0.5*(vol + acc), each element written exactly once
        size_t line = (((size_t)(b * C_DIM) * H_DIM + x) * H_DIM + (unsigned)y)
                      * (H_DIM / 4) + lane;
        #define EPI(C, ACC)                                                     \
            {                                                                   \
                size_t o = line + (size_t)(C) * cstr;                           \
                float4 v = __ldg(vol4 + o);                                     \
                float4 rr;                                                      \
                rr.x = (v.x + ACC.x) * 0.5f;                                    \
                rr.y = (v.y + ACC.y) * 0.5f;                                    \
                rr.z = (v.z + ACC.z) * 0.5f;                                    \
                rr.w = (v.w + ACC.w) * 0.5f;                                    \
                out4[o] = rr;                                                   \
            }
        EPI(0, acc0)
        EPI(1, acc1)
        EPI(2, acc2)
        EPI(3, acc3)
        #undef EPI
    }
}

extern "C" void kernel_launch(void* const* d_in, const int* in_sizes, int n_in,
                              void* d_out, int out_size) {
    const float4* patches = (const float4*)d_in[0];
    const float4* vol     = (const float4*)d_in[1];
    const int*    centers = (const int*)d_in[2];
    float4*       out     = (float4*)d_out;

    // 1024 blocks: (2 batches) x (128 x) x (4 y-quarters), 256 threads each
    pi_fused_kernel<<<1024, 256>>>(patches, vol, centers, out);
}

// round 7
// speedup vs baseline: 1.2756x; 1.2756x over previous
#include <cuda_runtime.h>
#include <cstdint>

// patches: [N=128, C=4, P=32, P, P] f32
// vol:     [B=2,  C=4, H=128, H, H] f32
// centers: [N, 3] i32 ; lower = center - 16 (in [0, 96])
// out = 0.5 * (vol + sum of covering patches)   -- gather, one pass, no atomics.

#define C_DIM 4
#define P_DIM 32
#define H_DIM 128

// per-patch strides in float4 units
#define PATCH_F4   32768u   // C*P^3/4
#define PC_F4      8192u    // P^3/4   (channel stride)
#define PI_F4      256u     // P^2/4   (i stride)
#define PJ_F4      8u       // P/4     (j stride)

// Block = (b, x, y-octave of 8): 2*128*16 = 4096 blocks of 256 threads.
// Block filters 64 patches to those overlapping (x, [y0,y0+7]) (~5 expected),
// then each of the 8 warps handles exactly one y-line against that short list.
__global__ void __launch_bounds__(256)
pi_fused_kernel(const float4* __restrict__ patches4,
                const float4* __restrict__ vol4,
                const int*    __restrict__ centers,
                float4*       __restrict__ out4)
{
    __shared__ int      s_cnt;
    __shared__ unsigned s_base[64];   // p*PATCH_F4 + dx*PI_F4 (float4 units)
    __shared__ int      s_lo1[64];
    __shared__ int      s_lo2[64];

    const unsigned blk  = blockIdx.x;
    const unsigned b    = blk >> 11;           // 2048 blocks per batch
    const unsigned rem  = blk & 2047u;
    const unsigned x    = rem >> 4;            // 0..127
    const unsigned y0   = (rem & 15u) << 3;    // 0,8,...,120
    const unsigned lane = threadIdx.x & 31u;
    const unsigned wid  = threadIdx.x >> 5;    // this warp's y = y0 + wid

    if (threadIdx.x == 0) s_cnt = 0;
    __syncthreads();

    // cooperative filter: threads 0..63 each test one patch of this batch
    if (threadIdx.x < 64u) {
        unsigned n = b * 64u + threadIdx.x;
        int lo0 = centers[n * 3 + 0] - (P_DIM / 2);
        int lo1 = centers[n * 3 + 1] - (P_DIM / 2);
        int lo2 = centers[n * 3 + 2] - (P_DIM / 2);
        unsigned dx = (unsigned)((int)x - lo0);
        bool hit_x = dx < 32u;
        bool hit_y = (unsigned)(lo1 - (int)y0 + 31) < 39u;  // overlaps [y0, y0+7]
        if (hit_x && hit_y) {
            int idx = atomicAdd(&s_cnt, 1);
            s_base[idx] = threadIdx.x * PATCH_F4 + dx * PI_F4;
            s_lo1[idx]  = lo1;
            s_lo2[idx]  = lo2;
        }
    }
    __syncthreads();

    const int ncand = s_cnt;
    const int y = (int)(y0 + wid);
    const float4 Z = make_float4(0.f,0.f,0.f,0.f);
    const float4* pb = patches4 + (size_t)b * 64u * PATCH_F4;
    const size_t cstr = (size_t)H_DIM * H_DIM * (H_DIM / 4);

    float4 acc0 = Z, acc1 = Z, acc2 = Z, acc3 = Z;

    #define ACCUM_CASE(EX0,EY0,EZ0,EW0)                                        \
        {                                                                       \
            const float4* pr0 = prow + 0u * PC_F4;                              \
            const float4* pr1 = prow + 1u * PC_F4;                              \
            const float4* pr2 = prow + 2u * PC_F4;                              \
            const float4* pr3 = prow + 3u * PC_F4;                              \
            float4 L0 = vL ? __ldg(pr0 + (m-1)) : Z;                            \
            float4 R0 = vR ? __ldg(pr0 + m)     : Z;                            \
            float4 L1 = vL ? __ldg(pr1 + (m-1)) : Z;                            \
            float4 R1 = vR ? __ldg(pr1 + m)     : Z;                            \
            float4 L2 = vL ? __ldg(pr2 + (m-1)) : Z;                            \
            float4 R2 = vR ? __ldg(pr2 + m)     : Z;                            \
            float4 L3 = vL ? __ldg(pr3 + (m-1)) : Z;                            \
            float4 R3 = vR ? __ldg(pr3 + m)     : Z;                            \
            acc0.x += EX0(L0,R0); acc0.y += EY0(L0,R0);                         \
            acc0.z += EZ0(L0,R0); acc0.w += EW0(L0,R0);                         \
            acc1.x += EX0(L1,R1); acc1.y += EY0(L1,R1);                         \
            acc1.z += EZ0(L1,R1); acc1.w += EW0(L1,R1);                         \
            acc2.x += EX0(L2,R2); acc2.y += EY0(L2,R2);                         \
            acc2.z += EZ0(L2,R2); acc2.w += EW0(L2,R2);                         \
            acc3.x += EX0(L3,R3); acc3.y += EY0(L3,R3);                         \
            acc3.z += EZ0(L3,R3); acc3.w += EW0(L3,R3);                         \
        }

    #define SEL_RX(L,R) (R.x)
    #define SEL_RY(L,R) (R.y)
    #define SEL_RZ(L,R) (R.z)
    #define SEL_RW(L,R) (R.w)
    #define SEL_LY(L,R) (L.y)
    #define SEL_LZ(L,R) (L.z)
    #define SEL_LW(L,R) (L.w)

    #pragma unroll 1
    for (int cI = 0; cI < ncand; cI++) {
        unsigned dy = (unsigned)(y - s_lo1[cI]);
        if (dy >= 32u) continue;              // warp-uniform
        const int lo2 = s_lo2[cI];
        const int m   = (int)lane - (lo2 >> 2);
        const unsigned s = (unsigned)lo2 & 3u;
        const bool vL = (unsigned)(m - 1) < 8u;
        const bool vR = (unsigned)m < 8u;
        const float4* prow = pb + s_base[cI] + dy * PJ_F4;

        switch (s) {                           // warp-uniform
        case 0u:  ACCUM_CASE(SEL_RX, SEL_RY, SEL_RZ, SEL_RW) break;
        case 1u:  ACCUM_CASE(SEL_LW, SEL_RX, SEL_RY, SEL_RZ) break;
        case 2u:  ACCUM_CASE(SEL_LZ, SEL_LW, SEL_RX, SEL_RY) break;
        default:  ACCUM_CASE(SEL_LY, SEL_LZ, SEL_LW, SEL_RX) break;
        }
    }

    // epilogue: out = 0.5*(vol + acc), each element written exactly once
    const size_t line = (((size_t)(b * C_DIM) * H_DIM + x) * H_DIM + (unsigned)y)
                        * (H_DIM / 4) + lane;
    #define EPI(C, ACC)                                                         \
        {                                                                       \
            size_t o = line + (size_t)(C) * cstr;                               \
            float4 v = __ldg(vol4 + o);                                         \
            float4 rr;                                                          \
            rr.x = (v.x + ACC.x) * 0.5f;                                        \
            rr.y = (v.y + ACC.y) * 0.5f;                                        \
            rr.z = (v.z + ACC.z) * 0.5f;                                        \
            rr.w = (v.w + ACC.w) * 0.5f;                                        \
            out4[o] = rr;                                                       \
        }
    EPI(0, acc0)
    EPI(1, acc1)
    EPI(2, acc2)
    EPI(3, acc3)
}

extern "C" void kernel_launch(void* const* d_in, const int* in_sizes, int n_in,
                              void* d_out, int out_size) {
    const float4* patches = (const float4*)d_in[0];
    const float4* vol     = (const float4*)d_in[1];
    const int*    centers = (const int*)d_in[2];
    float4*       out     = (float4*)d_out;

    // 4096 blocks: (2 batches) x (128 x) x (16 y-octaves), 256 threads each
    pi_fused_kernel<<<4096, 256>>>(patches, vol, centers, out);
}

// round 8
// speedup vs baseline: 1.4193x; 1.1127x over previous
#include <cuda_runtime.h>
#include <cstdint>

// patches: [N=128, C=4, P=32, P, P] f32
// vol:     [B=2,  C=4, H=128, H, H] f32
// centers: [N, 3] i32 ; lower = center - 16 (in [0, 96])
// out = 0.5 * (vol + sum of covering patches)   -- gather, one pass, no atomics.
// acc is initialized FROM vol (loads issued before the scan) so the vol-read
// latency overlaps the candidate filter + scan.

#define C_DIM 4
#define P_DIM 32
#define H_DIM 128

// per-patch strides in float4 units
#define PATCH_F4   32768u   // C*P^3/4
#define PC_F4      8192u    // P^3/4   (channel stride)
#define PI_F4      256u     // P^2/4   (i stride)
#define PJ_F4      8u       // P/4     (j stride)

// Block = (b, x, y-octave of 8): 2*128*16 = 4096 blocks of 256 threads.
__global__ void __launch_bounds__(256)
pi_fused_kernel(const float4* __restrict__ patches4,
                const float4* __restrict__ vol4,
                const int*    __restrict__ centers,
                float4*       __restrict__ out4)
{
    __shared__ int      s_cnt;
    __shared__ unsigned s_base[64];   // p*PATCH_F4 + dx*PI_F4 (float4 units)
    __shared__ int      s_lo1[64];
    __shared__ int      s_lo2[64];

    const unsigned blk  = blockIdx.x;
    const unsigned b    = blk >> 11;           // 2048 blocks per batch
    const unsigned rem  = blk & 2047u;
    const unsigned x    = rem >> 4;            // 0..127
    const unsigned y0   = (rem & 15u) << 3;    // 0,8,...,120
    const unsigned lane = threadIdx.x & 31u;
    const unsigned wid  = threadIdx.x >> 5;    // this warp's y = y0 + wid

    const int y = (int)(y0 + wid);
    const size_t cstr = (size_t)H_DIM * H_DIM * (H_DIM / 4);
    const size_t line = (((size_t)(b * C_DIM) * H_DIM + x) * H_DIM + (unsigned)y)
                        * (H_DIM / 4) + lane;

    // issue vol loads FIRST -- they stay in flight through filter + scan
    float4 acc0 = __ldg(vol4 + line + 0 * cstr);
    float4 acc1 = __ldg(vol4 + line + 1 * cstr);
    float4 acc2 = __ldg(vol4 + line + 2 * cstr);
    float4 acc3 = __ldg(vol4 + line + 3 * cstr);

    if (threadIdx.x == 0) s_cnt = 0;
    __syncthreads();

    // cooperative filter: threads 0..63 each test one patch of this batch
    if (threadIdx.x < 64u) {
        unsigned n = b * 64u + threadIdx.x;
        int lo0 = centers[n * 3 + 0] - (P_DIM / 2);
        int lo1 = centers[n * 3 + 1] - (P_DIM / 2);
        int lo2 = centers[n * 3 + 2] - (P_DIM / 2);
        unsigned dx = (unsigned)((int)x - lo0);
        bool hit_x = dx < 32u;
        bool hit_y = (unsigned)(lo1 - (int)y0 + 31) < 39u;  // overlaps [y0, y0+7]
        if (hit_x && hit_y) {
            int idx = atomicAdd(&s_cnt, 1);
            s_base[idx] = threadIdx.x * PATCH_F4 + dx * PI_F4;
            s_lo1[idx]  = lo1;
            s_lo2[idx]  = lo2;
        }
    }
    __syncthreads();

    const int ncand = s_cnt;
    const float4 Z = make_float4(0.f,0.f,0.f,0.f);
    const float4* pb = patches4 + (size_t)b * 64u * PATCH_F4;

    #define ACCUM_CASE(EX0,EY0,EZ0,EW0)                                        \
        {                                                                       \
            const float4* pr0 = prow + 0u * PC_F4;                              \
            const float4* pr1 = prow + 1u * PC_F4;                              \
            const float4* pr2 = prow + 2u * PC_F4;                              \
            const float4* pr3 = prow + 3u * PC_F4;                              \
            float4 L0 = vL ? __ldg(pr0 + (m-1)) : Z;                            \
            float4 R0 = vR ? __ldg(pr0 + m)     : Z;                            \
            float4 L1 = vL ? __ldg(pr1 + (m-1)) : Z;                            \
            float4 R1 = vR ? __ldg(pr1 + m)     : Z;                            \
            float4 L2 = vL ? __ldg(pr2 + (m-1)) : Z;                            \
            float4 R2 = vR ? __ldg(pr2 + m)     : Z;                            \
            float4 L3 = vL ? __ldg(pr3 + (m-1)) : Z;                            \
            float4 R3 = vR ? __ldg(pr3 + m)     : Z;                            \
            acc0.x += EX0(L0,R0); acc0.y += EY0(L0,R0);                         \
            acc0.z += EZ0(L0,R0); acc0.w += EW0(L0,R0);                         \
            acc1.x += EX0(L1,R1); acc1.y += EY0(L1,R1);                         \
            acc1.z += EZ0(L1,R1); acc1.w += EW0(L1,R1);                         \
            acc2.x += EX0(L2,R2); acc2.y += EY0(L2,R2);                         \
            acc2.z += EZ0(L2,R2); acc2.w += EW0(L2,R2);                         \
            acc3.x += EX0(L3,R3); acc3.y += EY0(L3,R3);                         \
            acc3.z += EZ0(L3,R3); acc3.w += EW0(L3,R3);                         \
        }

    #define SEL_RX(L,R) (R.x)
    #define SEL_RY(L,R) (R.y)
    #define SEL_RZ(L,R) (R.z)
    #define SEL_RW(L,R) (R.w)
    #define SEL_LY(L,R) (L.y)
    #define SEL_LZ(L,R) (L.z)
    #define SEL_LW(L,R) (L.w)

    #pragma unroll 1
    for (int cI = 0; cI < ncand; cI++) {
        unsigned dy = (unsigned)(y - s_lo1[cI]);
        if (dy >= 32u) continue;              // warp-uniform
        const int lo2 = s_lo2[cI];
        const int m   = (int)lane - (lo2 >> 2);
        const unsigned s = (unsigned)lo2 & 3u;
        const bool vL = (unsigned)(m - 1) < 8u;
        const bool vR = (unsigned)m < 8u;
        const float4* prow = pb + s_base[cI] + dy * PJ_F4;

        switch (s) {                           // warp-uniform
        case 0u:  ACCUM_CASE(SEL_RX, SEL_RY, SEL_RZ, SEL_RW) break;
        case 1u:  ACCUM_CASE(SEL_LW, SEL_RX, SEL_RY, SEL_RZ) break;
        case 2u:  ACCUM_CASE(SEL_LZ, SEL_LW, SEL_RX, SEL_RY) break;
        default:  ACCUM_CASE(SEL_LY, SEL_LZ, SEL_LW, SEL_RX) break;
        }
    }

    // epilogue: out = 0.5 * acc   (acc already contains vol + patch sums)
    #define EPI(C, ACC)                                                         \
        {                                                                       \
            size_t o = line + (size_t)(C) * cstr;                               \
            float4 rr;                                                          \
            rr.x = ACC.x * 0.5f;                                                \
            rr.y = ACC.y * 0.5f;                                                \
            rr.z = ACC.z * 0.5f;                                                \
            rr.w = ACC.w * 0.5f;                                                \
            out4[o] = rr;                                                       \
        }
    EPI(0, acc0)
    EPI(1, acc1)
    EPI(2, acc2)
    EPI(3, acc3)
}

extern "C" void kernel_launch(void* const* d_in, const int* in_sizes, int n_in,
                              void* d_out, int out_size) {
    const float4* patches = (const float4*)d_in[0];
    const float4* vol     = (const float4*)d_in[1];
    const int*    centers = (const int*)d_in[2];
    float4*       out     = (float4*)d_out;

    // 4096 blocks: (2 batches) x (128 x) x (16 y-octaves), 256 threads each
    pi_fused_kernel<<<4096, 256>>>(patches, vol, centers, out);
}

// round 9
// speedup vs baseline: 1.8008x; 1.2688x over previous
#include <cuda_runtime.h>
#include <cstdint>

// patches: [N=128, C=4, P=32, P, P] f32
// vol:     [B=2,  C=4, H=128, H, H] f32
// centers: [N, 3] i32 ; lower = center - 16 (in [0, 96])
// out = 0.5 * (vol + sum of covering patches)   -- gather, one pass, no atomics.
// Patch rows are staged into smem with cp.async (register-free MLP), then
// accumulated from smem. vol is preloaded into the accumulators up front.

#define C_DIM 4
#define P_DIM 32
#define H_DIM 128

// per-patch strides in float4 units
#define PATCH_F4   32768u   // C*P^3/4
#define PC_F4      8192u    // P^3/4   (channel stride)
#define PI_F4      256u     // P^2/4   (i stride)
#define PJ_F4      8u       // P/4     (j stride)

#define S_SLOTS    8        // staged hits per warp (fallback beyond)
#define SLOT_BYTES 512      // 4 channels x 128B row

// Block = (b, x, y-octave of 8): 2*128*16 = 4096 blocks of 256 threads.
__global__ void __launch_bounds__(256)
pi_fused_kernel(const float4* __restrict__ patches4,
                const float4* __restrict__ vol4,
                const int*    __restrict__ centers,
                float4*       __restrict__ out4)
{
    __shared__ int      s_cnt;
    __shared__ unsigned s_base[64];   // p*PATCH_F4 + dx*PI_F4 (float4 units)
    __shared__ int      s_lo1[64];
    __shared__ int      s_lo2[64];
    __shared__ __align__(16) char s_stage[8 * S_SLOTS * SLOT_BYTES];  // 32 KB

    const unsigned blk  = blockIdx.x;
    const unsigned b    = blk >> 11;           // 2048 blocks per batch
    const unsigned rem  = blk & 2047u;
    const unsigned x    = rem >> 4;            // 0..127
    const unsigned y0   = (rem & 15u) << 3;    // 0,8,...,120
    const unsigned lane = threadIdx.x & 31u;
    const unsigned wid  = threadIdx.x >> 5;    // this warp's y = y0 + wid

    const int y = (int)(y0 + wid);
    const size_t cstr = (size_t)H_DIM * H_DIM * (H_DIM / 4);
    const size_t line = (((size_t)(b * C_DIM) * H_DIM + x) * H_DIM + (unsigned)y)
                        * (H_DIM / 4) + lane;

    // vol loads issued first -- in flight through filter + staging + scan
    float4 acc0 = __ldg(vol4 + line + 0 * cstr);
    float4 acc1 = __ldg(vol4 + line + 1 * cstr);
    float4 acc2 = __ldg(vol4 + line + 2 * cstr);
    float4 acc3 = __ldg(vol4 + line + 3 * cstr);

    if (threadIdx.x == 0) s_cnt = 0;
    __syncthreads();

    // cooperative filter: threads 0..63 each test one patch of this batch
    if (threadIdx.x < 64u) {
        unsigned n = b * 64u + threadIdx.x;
        int lo0 = centers[n * 3 + 0] - (P_DIM / 2);
        int lo1 = centers[n * 3 + 1] - (P_DIM / 2);
        int lo2 = centers[n * 3 + 2] - (P_DIM / 2);
        unsigned dx = (unsigned)((int)x - lo0);
        bool hit_x = dx < 32u;
        bool hit_y = (unsigned)(lo1 - (int)y0 + 31) < 39u;  // overlaps [y0, y0+7]
        if (hit_x && hit_y) {
            int idx = atomicAdd(&s_cnt, 1);
            s_base[idx] = threadIdx.x * PATCH_F4 + dx * PI_F4;
            s_lo1[idx]  = lo1;
            s_lo2[idx]  = lo2;
        }
    }
    __syncthreads();

    const int ncand = s_cnt;
    const float4 Z = make_float4(0.f,0.f,0.f,0.f);
    const float4* pb = patches4 + (size_t)b * 64u * PATCH_F4;

    // ---- phase 1: stage hit rows into smem via cp.async (no dest registers) ----
    // lane -> (channel = lane>>3, quad = lane&7): one warp-wide cp.async moves
    // the full 4x128B needed for a hit.
    char* warp_stage = s_stage + (size_t)wid * (S_SLOTS * SLOT_BYTES);
    {
        const unsigned c_l = lane >> 3;
        const unsigned q_l = lane & 7u;
        unsigned dst0 = (unsigned)__cvta_generic_to_shared(warp_stage) + lane * 16u;
        unsigned q = 0;
        #pragma unroll 1
        for (int cI = 0; cI < ncand; cI++) {
            unsigned dy = (unsigned)(y - s_lo1[cI]);
            if (dy >= 32u) continue;              // warp-uniform
            if (q < S_SLOTS) {
                const float4* gsrc = pb + s_base[cI] + dy * PJ_F4
                                   + c_l * PC_F4 + q_l;
                unsigned dst = dst0 + q * SLOT_BYTES;
                asm volatile("cp.async.ca.shared.global [%0], [%1], 16;"
                             :: "r"(dst), "l"(gsrc));
            }
            q++;
        }
        asm volatile("cp.async.wait_all;" ::: "memory");
        __syncwarp();
    }

    // ---- phase 2: accumulate from smem (fallback: direct LDG past S_SLOTS) ----
    #define ACCUM_BODY(LD_L, LD_R, EX0,EY0,EZ0,EW0)                             \
        {                                                                       \
            float4 L0 = vL ? LD_L(0) : Z;                                       \
            float4 R0 = vR ? LD_R(0) : Z;                                       \
            float4 L1 = vL ? LD_L(1) : Z;                                       \
            float4 R1 = vR ? LD_R(1) : Z;                                       \
            float4 L2 = vL ? LD_L(2) : Z;                                       \
            float4 R2 = vR ? LD_R(2) : Z;                                       \
            float4 L3 = vL ? LD_L(3) : Z;                                       \
            float4 R3 = vR ? LD_R(3) : Z;                                       \
            acc0.x += EX0(L0,R0); acc0.y += EY0(L0,R0);                         \
            acc0.z += EZ0(L0,R0); acc0.w += EW0(L0,R0);                         \
            acc1.x += EX0(L1,R1); acc1.y += EY0(L1,R1);                         \
            acc1.z += EZ0(L1,R1); acc1.w += EW0(L1,R1);                         \
            acc2.x += EX0(L2,R2); acc2.y += EY0(L2,R2);                         \
            acc2.z += EZ0(L2,R2); acc2.w += EW0(L2,R2);                         \
            acc3.x += EX0(L3,R3); acc3.y += EY0(L3,R3);                         \
            acc3.z += EZ0(L3,R3); acc3.w += EW0(L3,R3);                         \
        }

    #define SEL_RX(L,R) (R.x)
    #define SEL_RY(L,R) (R.y)
    #define SEL_RZ(L,R) (R.z)
    #define SEL_RW(L,R) (R.w)
    #define SEL_LY(L,R) (L.y)
    #define SEL_LZ(L,R) (L.z)
    #define SEL_LW(L,R) (L.w)

    #define LDS_L(C) (sl[(C) * 8 + (m - 1)])
    #define LDS_R(C) (sl[(C) * 8 + m])
    #define LDG_L(C) (__ldg(prow + (C) * PC_F4 + (m - 1)))
    #define LDG_R(C) (__ldg(prow + (C) * PC_F4 + m))

    {
        unsigned q = 0;
        #pragma unroll 1
        for (int cI = 0; cI < ncand; cI++) {
            unsigned dy = (unsigned)(y - s_lo1[cI]);
            if (dy >= 32u) continue;              // warp-uniform
            const int lo2 = s_lo2[cI];
            const int m   = (int)lane - (lo2 >> 2);
            const unsigned s = (unsigned)lo2 & 3u;
            const bool vL = (unsigned)(m - 1) < 8u;
            const bool vR = (unsigned)m < 8u;

            if (q < S_SLOTS) {
                const float4* sl = (const float4*)(warp_stage + q * SLOT_BYTES);
                switch (s) {                       // warp-uniform
                case 0u:  ACCUM_BODY(LDS_L, LDS_R, SEL_RX, SEL_RY, SEL_RZ, SEL_RW) break;
                case 1u:  ACCUM_BODY(LDS_L, LDS_R, SEL_LW, SEL_RX, SEL_RY, SEL_RZ) break;
                case 2u:  ACCUM_BODY(LDS_L, LDS_R, SEL_LZ, SEL_LW, SEL_RX, SEL_RY) break;
                default:  ACCUM_BODY(LDS_L, LDS_R, SEL_LY, SEL_LZ, SEL_LW, SEL_RX) break;
                }
            } else {                               // rare overflow fallback
                const float4* prow = pb + s_base[cI] + dy * PJ_F4;
                switch (s) {
                case 0u:  ACCUM_BODY(LDG_L, LDG_R, SEL_RX, SEL_RY, SEL_RZ, SEL_RW) break;
                case 1u:  ACCUM_BODY(LDG_L, LDG_R, SEL_LW, SEL_RX, SEL_RY, SEL_RZ) break;
                case 2u:  ACCUM_BODY(LDG_L, LDG_R, SEL_LZ, SEL_LW, SEL_RX, SEL_RY) break;
                default:  ACCUM_BODY(LDG_L, LDG_R, SEL_LY, SEL_LZ, SEL_LW, SEL_RX) break;
                }
            }
            q++;
        }
    }

    // epilogue: out = 0.5 * acc   (acc already contains vol + patch sums)
    #define EPI(C, ACC)                                                         \
        {                                                                       \
            size_t o = line + (size_t)(C) * cstr;                               \
            float4 rr;                                                          \
            rr.x = ACC.x * 0.5f;                                                \
            rr.y = ACC.y * 0.5f;                                                \
            rr.z = ACC.z * 0.5f;                                                \
            rr.w = ACC.w * 0.5f;                                                \
            out4[o] = rr;                                                       \
        }
    EPI(0, acc0)
    EPI(1, acc1)
    EPI(2, acc2)
    EPI(3, acc3)
}

extern "C" void kernel_launch(void* const* d_in, const int* in_sizes, int n_in,
                              void* d_out, int out_size) {
    const float4* patches = (const float4*)d_in[0];
    const float4* vol     = (const float4*)d_in[1];
    const int*    centers = (const int*)d_in[2];
    float4*       out     = (float4*)d_out;

    // 4096 blocks: (2 batches) x (128 x) x (16 y-octaves), 256 threads each
    pi_fused_kernel<<<4096, 256>>>(patches, vol, centers, out);
}